// round 1
// baseline (speedup 1.0000x reference)
#include <cuda_runtime.h>

// Problem dims
#define BB   32
#define NN   1024
#define FIN  512
#define H1D  256
#define H2D  128

#define ROWS (BB * NN)   // 32768

// ---------------- scratch (static device globals; no allocation) ----------------
__device__ float d_h1 [ROWS * H1D];        // x @ W1
__device__ float d_g1 [ROWS * H1D];        // elu(att1 @ h1)
__device__ float d_h2 [ROWS * H2D];        // g1 @ W2
__device__ float d_att1[BB * NN * NN];     // layer-1 attention (134 MB)
__device__ float d_el1[ROWS], d_er1[ROWS];
__device__ float d_el2[ROWS], d_er2[ROWS];
__device__ float d_gz [ROWS];              // g2 @ Wg
__device__ float d_prm1[2 * BB];           // {mn, 30/(mx-mn)} per batch
__device__ float d_prm2[2 * BB];

// ---------------- generic fp32 tiled GEMM: C[M,N] = A[M,K] @ B[K,N] ----------------
// 64x64 tile, BK=16, 256 threads, 4x4 per thread. Requires M%64==0, N%64==0, K%16==0.
// EPI: 0 = none, 1 = ELU
template<int EPI>
__global__ void gemm64(const float* __restrict__ A, const float* __restrict__ Bm,
                       float* __restrict__ C, int M, int N, int K,
                       long sA, long sB, long sC)
{
    __shared__ float As[16][68];
    __shared__ float Bs[16][68];

    const float* Ab = A  + (long)blockIdx.z * sA;
    const float* Bb = Bm + (long)blockIdx.z * sB;
    float*       Cb = C  + (long)blockIdx.z * sC;

    const int tid = threadIdx.x;
    const int tx  = tid & 15;
    const int ty  = tid >> 4;
    const int m0  = blockIdx.y * 64;
    const int n0  = blockIdx.x * 64;

    float acc[4][4] = {};

    for (int k0 = 0; k0 < K; k0 += 16) {
        // A tile: 64 rows x 16 k, stored transposed As[k][m]
        {
            int r = tid >> 2;          // 0..63
            int c = (tid & 3) * 4;     // 0,4,8,12
            float4 v = *reinterpret_cast<const float4*>(Ab + (long)(m0 + r) * K + k0 + c);
            As[c + 0][r] = v.x; As[c + 1][r] = v.y;
            As[c + 2][r] = v.z; As[c + 3][r] = v.w;
        }
        // B tile: 16 k x 64 n
        {
            int r = tid >> 4;          // 0..15
            int c = (tid & 15) * 4;    // 0..60
            float4 v = *reinterpret_cast<const float4*>(Bb + (long)(k0 + r) * N + n0 + c);
            Bs[r][c + 0] = v.x; Bs[r][c + 1] = v.y;
            Bs[r][c + 2] = v.z; Bs[r][c + 3] = v.w;
        }
        __syncthreads();

        #pragma unroll
        for (int k = 0; k < 16; k++) {
            float4 av = *reinterpret_cast<const float4*>(&As[k][ty * 4]);
            float4 bv = *reinterpret_cast<const float4*>(&Bs[k][tx * 4]);
            float a[4] = {av.x, av.y, av.z, av.w};
            float b[4] = {bv.x, bv.y, bv.z, bv.w};
            #pragma unroll
            for (int i = 0; i < 4; i++)
                #pragma unroll
                for (int j = 0; j < 4; j++)
                    acc[i][j] = fmaf(a[i], b[j], acc[i][j]);
        }
        __syncthreads();
    }

    #pragma unroll
    for (int i = 0; i < 4; i++) {
        int row = m0 + ty * 4 + i;
        float4 v;
        float* p = &v.x;
        #pragma unroll
        for (int j = 0; j < 4; j++) {
            float x = acc[i][j];
            if (EPI == 1) x = (x > 0.0f) ? x : (expm1f(x));
            p[j] = x;
        }
        *reinterpret_cast<float4*>(Cb + (long)row * N + n0 + tx * 4) = v;
    }
}

// ---------------- el/er row dots: el[r]=h[r].aL, er[r]=h[r].aR (warp per row) ------
__global__ void rowdots(const float* __restrict__ H, const float* __restrict__ a,
                        float* __restrict__ el, float* __restrict__ er, int Fo)
{
    int row  = blockIdx.x * (blockDim.x >> 5) + (threadIdx.x >> 5);
    int lane = threadIdx.x & 31;
    const float* h = H + (long)row * Fo;
    float sl = 0.f, sr = 0.f;
    for (int c = lane; c < Fo; c += 32) {
        float hv = h[c];
        sl = fmaf(hv, a[c], sl);
        sr = fmaf(hv, a[Fo + c], sr);
    }
    #pragma unroll
    for (int o = 16; o; o >>= 1) {
        sl += __shfl_xor_sync(0xffffffffu, sl, o);
        sr += __shfl_xor_sync(0xffffffffu, sr, o);
    }
    if (lane == 0) { el[row] = sl; er[row] = sr; }
}

// ---------------- per-batch min/max -> {mn, 30/(mx-mn)} ---------------------------
__global__ void minmax_kernel(const float* __restrict__ el, const float* __restrict__ er,
                              float* __restrict__ prm)
{
    __shared__ float sm[4][8];
    int b = blockIdx.x, tid = threadIdx.x;  // 256 threads
    float mnl =  3.4e38f, mxl = -3.4e38f, mnr = 3.4e38f, mxr = -3.4e38f;
    for (int i = tid; i < NN; i += 256) {
        float v = el[b * NN + i]; mnl = fminf(mnl, v); mxl = fmaxf(mxl, v);
        float w = er[b * NN + i]; mnr = fminf(mnr, w); mxr = fmaxf(mxr, w);
    }
    #pragma unroll
    for (int o = 16; o; o >>= 1) {
        mnl = fminf(mnl, __shfl_xor_sync(0xffffffffu, mnl, o));
        mxl = fmaxf(mxl, __shfl_xor_sync(0xffffffffu, mxl, o));
        mnr = fminf(mnr, __shfl_xor_sync(0xffffffffu, mnr, o));
        mxr = fmaxf(mxr, __shfl_xor_sync(0xffffffffu, mxr, o));
    }
    int wid = tid >> 5, lane = tid & 31;
    if (lane == 0) { sm[0][wid] = mnl; sm[1][wid] = mxl; sm[2][wid] = mnr; sm[3][wid] = mxr; }
    __syncthreads();
    if (tid == 0) {
        float a = sm[0][0], c = sm[1][0], d = sm[2][0], e = sm[3][0];
        for (int w = 1; w < 8; w++) {
            a = fminf(a, sm[0][w]); c = fmaxf(c, sm[1][w]);
            d = fminf(d, sm[2][w]); e = fmaxf(e, sm[3][w]);
        }
        float smn = a + d, smx = c + e;                       // leaky is monotone
        float emn = (smn >= 0.f) ? smn : 0.01f * smn;
        float emx = (smx >= 0.f) ? smx : 0.01f * smx;
        prm[2 * b]     = emn;
        prm[2 * b + 1] = 30.0f / (emx - emn);
    }
}

// ---------------- attention materialization: att = sigmoid(norm(leaky(el+er))) ----
__global__ void att_kernel(const float* __restrict__ el, const float* __restrict__ er,
                           const float* __restrict__ prm, float* __restrict__ att)
{
    long idx = (long)blockIdx.x * blockDim.x + threadIdx.x;   // < 2^25
    int b = (int)(idx >> 20);
    int rem = (int)(idx & ((1 << 20) - 1));
    int i = rem >> 10, j = rem & 1023;
    float e = el[b * NN + i] + er[b * NN + j];
    e = (e >= 0.f) ? e : 0.01f * e;
    float t = (e - prm[2 * b]) * prm[2 * b + 1] - 20.0f;
    att[idx] = 1.0f / (1.0f + __expf(-t));
}

// ---------------- gz[r] = g2[r,:] . Wg (warp per row, Fo=128) ---------------------
__global__ void gz_kernel(const float* __restrict__ g2, const float* __restrict__ Wg,
                          float* __restrict__ gz)
{
    int row  = blockIdx.x * (blockDim.x >> 5) + (threadIdx.x >> 5);
    int lane = threadIdx.x & 31;
    const float* g = g2 + (long)row * H2D;
    float s = 0.f;
    for (int c = lane; c < H2D; c += 32) s = fmaf(g[c], Wg[c], s);
    #pragma unroll
    for (int o = 16; o; o >>= 1) s += __shfl_xor_sync(0xffffffffu, s, o);
    if (lane == 0) gz[row] = s;
}

// ---------------- out[b,i] = leaky( fc2[b,i,:] . gz[b,:] + bg ) -------------------
__global__ void final_out(const float* __restrict__ fc2, const float* __restrict__ gz,
                          const float* __restrict__ bg, float* __restrict__ out)
{
    int row  = blockIdx.x * (blockDim.x >> 5) + (threadIdx.x >> 5);  // 0..32767
    int lane = threadIdx.x & 31;
    int b = row >> 10;
    const float* f = fc2 + (long)row * NN;
    const float* g = gz + b * NN;
    float s = 0.f;
    for (int j = lane; j < NN; j += 32) s = fmaf(f[j], g[j], s);
    #pragma unroll
    for (int o = 16; o; o >>= 1) s += __shfl_xor_sync(0xffffffffu, s, o);
    if (lane == 0) {
        float z = s + bg[0];
        out[row] = (z >= 0.f) ? z : 0.01f * z;
    }
}

// ------------------------------- launch ------------------------------------------
extern "C" void kernel_launch(void* const* d_in, const int* in_sizes, int n_in,
                              void* d_out, int out_size)
{
    const float* x  = (const float*)d_in[0];
    // d_in[1] = edge_weight: unused by the reference
    const float* W1 = (const float*)d_in[2];
    const float* a1 = (const float*)d_in[3];
    const float* W2 = (const float*)d_in[4];
    const float* a2 = (const float*)d_in[5];
    const float* Wg = (const float*)d_in[6];
    const float* bg = (const float*)d_in[7];

    float* out_z  = (float*)d_out;                       // [B,N,1]   = 32768
    float* fc2    = out_z + ROWS;                        // [B,N,N]   = 33554432
    float* g2     = fc2 + (long)BB * NN * NN;            // [B,N,H2]  = 4194304

    float *p_h1, *p_g1, *p_h2, *p_att1, *p_el1, *p_er1, *p_el2, *p_er2,
          *p_gz, *p_prm1, *p_prm2;
    cudaGetSymbolAddress((void**)&p_h1,   d_h1);
    cudaGetSymbolAddress((void**)&p_g1,   d_g1);
    cudaGetSymbolAddress((void**)&p_h2,   d_h2);
    cudaGetSymbolAddress((void**)&p_att1, d_att1);
    cudaGetSymbolAddress((void**)&p_el1,  d_el1);
    cudaGetSymbolAddress((void**)&p_er1,  d_er1);
    cudaGetSymbolAddress((void**)&p_el2,  d_el2);
    cudaGetSymbolAddress((void**)&p_er2,  d_er2);
    cudaGetSymbolAddress((void**)&p_gz,   d_gz);
    cudaGetSymbolAddress((void**)&p_prm1, d_prm1);
    cudaGetSymbolAddress((void**)&p_prm2, d_prm2);

    // 1) h1 = x @ W1         [32768,512]@[512,256]
    gemm64<0><<<dim3(H1D / 64, ROWS / 64, 1), 256>>>(x, W1, p_h1, ROWS, H1D, FIN, 0, 0, 0);

    // 2) el1/er1 = h1 . a1L/a1R
    rowdots<<<ROWS / 8, 256>>>(p_h1, a1, p_el1, p_er1, H1D);

    // 3) per-batch min/max -> normalization params (leaky is monotone)
    minmax_kernel<<<BB, 256>>>(p_el1, p_er1, p_prm1);

    // 4) att1 = sigmoid(norm(leaky(el+er)))
    att_kernel<<<(BB * NN * NN) / 256, 256>>>(p_el1, p_er1, p_prm1, p_att1);

    // 5) g1 = elu(att1 @ h1)  batched [1024,1024]@[1024,256]
    gemm64<1><<<dim3(H1D / 64, NN / 64, BB), 256>>>(p_att1, p_h1, p_g1, NN, H1D, NN,
                                                    (long)NN * NN, (long)NN * H1D, (long)NN * H1D);

    // 6) h2 = g1 @ W2         [32768,256]@[256,128]
    gemm64<0><<<dim3(H2D / 64, ROWS / 64, 1), 256>>>(p_g1, W2, p_h2, ROWS, H2D, H1D, 0, 0, 0);

    // 7) el2/er2
    rowdots<<<ROWS / 8, 256>>>(p_h2, a2, p_el2, p_er2, H2D);

    // 8) minmax layer 2
    minmax_kernel<<<BB, 256>>>(p_el2, p_er2, p_prm2);

    // 9) fc2 (output) = att2
    att_kernel<<<(BB * NN * NN) / 256, 256>>>(p_el2, p_er2, p_prm2, fc2);

    // 10) g2 (output) = att2 @ h2   batched [1024,1024]@[1024,128]
    gemm64<0><<<dim3(H2D / 64, NN / 64, BB), 256>>>(fc2, p_h2, g2, NN, H2D, NN,
                                                    (long)NN * NN, (long)NN * H2D, (long)NN * H2D);

    // 11) gz = g2 @ Wg   (associativity: (fc2@g2)@Wg == fc2@(g2@Wg))
    gz_kernel<<<ROWS / 8, 256>>>(g2, Wg, p_gz);

    // 12) out = leaky(fc2 @ gz + bg)
    final_out<<<ROWS / 8, 256>>>(fc2, p_gz, bg, out_z);
}

// round 4
// speedup vs baseline: 1.8690x; 1.8690x over previous
#include <cuda_runtime.h>

#define BB   32
#define NN   1024
#define FIN  512
#define H1D  256
#define H2D  128
#define ROWS (BB * NN)   // 32768

// ---------------- scratch ----------------
__device__ float d_h1 [ROWS * H1D];
__device__ float d_g1 [ROWS * H1D];
__device__ float d_h2 [ROWS * H2D];
__device__ float d_el1[ROWS], d_er1[ROWS];
__device__ float d_el2[ROWS], d_er2[ROWS];
__device__ float d_gz [ROWS];
__device__ float d_prm1[2 * BB];
__device__ float d_prm2[2 * BB];

// =================================================================================
// Plain fp32 GEMM: C[M,N] = A[M,K] @ B[K,N].  128x128 tile, BK=16, 256 thr, 8x8.
// Double-buffered smem. Requires M%128==0, N%128==0, K%16==0.
// =================================================================================
__global__ __launch_bounds__(256, 2)
void gemm128(const float* __restrict__ A, const float* __restrict__ B,
             float* __restrict__ C, int M, int N, int K)
{
    __shared__ float As[2][16][132];
    __shared__ float Bs[2][16][132];

    const int tid = threadIdx.x;
    const int tx = tid & 15, ty = tid >> 4;
    const int m0 = blockIdx.y * 128, n0 = blockIdx.x * 128;

    const int ar = tid >> 1, ak = (tid & 1) * 8;   // A: row in tile, k-offset
    const int br = tid >> 4, bc = (tid & 15) * 8;  // B: k-row, col

    float acc[8][8] = {};
    float4 la0, la1, lb0, lb1;

    // prologue: load tile 0
    la0 = *(const float4*)(A + (long)(m0 + ar) * K + ak);
    la1 = *(const float4*)(A + (long)(m0 + ar) * K + ak + 4);
    lb0 = *(const float4*)(B + (long)br * N + n0 + bc);
    lb1 = *(const float4*)(B + (long)br * N + n0 + bc + 4);
    {
        float av[8] = {la0.x, la0.y, la0.z, la0.w, la1.x, la1.y, la1.z, la1.w};
        #pragma unroll
        for (int i = 0; i < 8; i++) As[0][ak + i][ar] = av[i];
        *(float4*)&Bs[0][br][bc]     = lb0;
        *(float4*)&Bs[0][br][bc + 4] = lb1;
    }
    __syncthreads();

    const int kt = K >> 4;
    for (int t = 0; t < kt; t++) {
        const int cur = t & 1, nxt = cur ^ 1;
        if (t + 1 < kt) {
            int k0 = (t + 1) << 4;
            la0 = *(const float4*)(A + (long)(m0 + ar) * K + k0 + ak);
            la1 = *(const float4*)(A + (long)(m0 + ar) * K + k0 + ak + 4);
            lb0 = *(const float4*)(B + (long)(k0 + br) * N + n0 + bc);
            lb1 = *(const float4*)(B + (long)(k0 + br) * N + n0 + bc + 4);
        }
        #pragma unroll
        for (int k = 0; k < 16; k++) {
            float4 xa = *(const float4*)&As[cur][k][ty * 4];
            float4 xb = *(const float4*)&As[cur][k][64 + ty * 4];
            float4 ya = *(const float4*)&Bs[cur][k][tx * 4];
            float4 yb = *(const float4*)&Bs[cur][k][64 + tx * 4];
            float am[8] = {xa.x, xa.y, xa.z, xa.w, xb.x, xb.y, xb.z, xb.w};
            float bn[8] = {ya.x, ya.y, ya.z, ya.w, yb.x, yb.y, yb.z, yb.w};
            #pragma unroll
            for (int i = 0; i < 8; i++)
                #pragma unroll
                for (int j = 0; j < 8; j++)
                    acc[i][j] = fmaf(am[i], bn[j], acc[i][j]);
        }
        if (t + 1 < kt) {
            float av[8] = {la0.x, la0.y, la0.z, la0.w, la1.x, la1.y, la1.z, la1.w};
            #pragma unroll
            for (int i = 0; i < 8; i++) As[nxt][ak + i][ar] = av[i];
            *(float4*)&Bs[nxt][br][bc]     = lb0;
            *(float4*)&Bs[nxt][br][bc + 4] = lb1;
        }
        __syncthreads();
    }

    #pragma unroll
    for (int i = 0; i < 8; i++) {
        int m = m0 + ((i < 4) ? (ty * 4 + i) : (64 + ty * 4 + i - 4));
        float4 v0 = {acc[i][0], acc[i][1], acc[i][2], acc[i][3]};
        float4 v1 = {acc[i][4], acc[i][5], acc[i][6], acc[i][7]};
        *(float4*)(C + (long)m * N + n0 + tx * 4)      = v0;
        *(float4*)(C + (long)m * N + n0 + 64 + tx * 4) = v1;
    }
}

// =================================================================================
// Fused attention GEMM: C_b = att_b @ H_b per batch, att computed on the fly from
// el/er/prm. Optionally writes att tile to attOut (fc2) and applies ELU epilogue.
// Tile 128x128, BK=16, 256 threads, 8x8 per thread, double-buffered.
// Grid: (fo/128, NN/128, BB)
// =================================================================================
template<int WRITE_ATT, int EPI>
__global__ __launch_bounds__(256, 2)
void attgemm(const float* __restrict__ el, const float* __restrict__ er,
             const float* __restrict__ prm, const float* __restrict__ H,
             float* __restrict__ C, float* __restrict__ attOut, int fo)
{
    __shared__ float As[2][16][132];
    __shared__ float Bs[2][16][132];
    __shared__ float el_s[128];

    const int tid = threadIdx.x;
    const int tx = tid & 15, ty = tid >> 4;
    const int b = blockIdx.z, m0 = blockIdx.y * 128, n0 = blockIdx.x * 128;

    const float* Hb  = H + (long)b * NN * fo;
    float*       Cb  = C + (long)b * NN * fo;
    const float* erb = er + b * NN;
    const float  mn  = prm[2 * b];
    const float  sc  = prm[2 * b + 1];

    if (tid < 128) el_s[tid] = el[b * NN + m0 + tid];
    __syncthreads();

    const int ar = tid >> 1, ak = (tid & 1) * 8;
    const int br = tid >> 4, bc = (tid & 15) * 8;
    const float elv = el_s[ar];

    float acc[8][8] = {};
    float av[8];
    float4 lb0, lb1;

    // --- att generation for A tile (8 values along k at (m0+ar, k0+ak..)) ---
    auto gen_att = [&](int k0) {
        float4 e0 = *(const float4*)(erb + k0 + ak);
        float4 e1 = *(const float4*)(erb + k0 + ak + 4);
        float ee[8] = {e0.x, e0.y, e0.z, e0.w, e1.x, e1.y, e1.z, e1.w};
        #pragma unroll
        for (int i = 0; i < 8; i++) {
            float e = elv + ee[i];
            e = (e >= 0.0f) ? e : 0.01f * e;
            float tt = (e - mn) * sc - 20.0f;
            av[i] = 1.0f / (1.0f + __expf(-tt));
        }
        if (WRITE_ATT) {
            float4 w0 = {av[0], av[1], av[2], av[3]};
            float4 w1 = {av[4], av[5], av[6], av[7]};
            float* dst = attOut + ((long)b * NN + m0 + ar) * NN + k0 + ak;
            *(float4*)dst       = w0;
            *(float4*)(dst + 4) = w1;
        }
    };

    // prologue
    gen_att(0);
    lb0 = *(const float4*)(Hb + (long)br * fo + n0 + bc);
    lb1 = *(const float4*)(Hb + (long)br * fo + n0 + bc + 4);
    {
        #pragma unroll
        for (int i = 0; i < 8; i++) As[0][ak + i][ar] = av[i];
        *(float4*)&Bs[0][br][bc]     = lb0;
        *(float4*)&Bs[0][br][bc + 4] = lb1;
    }
    __syncthreads();

    const int kt = NN >> 4;   // 64
    for (int t = 0; t < kt; t++) {
        const int cur = t & 1, nxt = cur ^ 1;
        if (t + 1 < kt) {
            int k0 = (t + 1) << 4;
            gen_att(k0);
            lb0 = *(const float4*)(Hb + (long)(k0 + br) * fo + n0 + bc);
            lb1 = *(const float4*)(Hb + (long)(k0 + br) * fo + n0 + bc + 4);
        }
        #pragma unroll
        for (int k = 0; k < 16; k++) {
            float4 xa = *(const float4*)&As[cur][k][ty * 4];
            float4 xb = *(const float4*)&As[cur][k][64 + ty * 4];
            float4 ya = *(const float4*)&Bs[cur][k][tx * 4];
            float4 yb = *(const float4*)&Bs[cur][k][64 + tx * 4];
            float am[8] = {xa.x, xa.y, xa.z, xa.w, xb.x, xb.y, xb.z, xb.w};
            float bn[8] = {ya.x, ya.y, ya.z, ya.w, yb.x, yb.y, yb.z, yb.w};
            #pragma unroll
            for (int i = 0; i < 8; i++)
                #pragma unroll
                for (int j = 0; j < 8; j++)
                    acc[i][j] = fmaf(am[i], bn[j], acc[i][j]);
        }
        if (t + 1 < kt) {
            #pragma unroll
            for (int i = 0; i < 8; i++) As[nxt][ak + i][ar] = av[i];
            *(float4*)&Bs[nxt][br][bc]     = lb0;
            *(float4*)&Bs[nxt][br][bc + 4] = lb1;
        }
        __syncthreads();
    }

    #pragma unroll
    for (int i = 0; i < 8; i++) {
        int m = (i < 4) ? (ty * 4 + i) : (64 + ty * 4 + i - 4);
        float vals[8];
        #pragma unroll
        for (int j = 0; j < 8; j++) {
            float v = acc[i][j];
            if (EPI == 1) v = (v > 0.0f) ? v : (__expf(v) - 1.0f);
            vals[j] = v;
        }
        float4 v0 = {vals[0], vals[1], vals[2], vals[3]};
        float4 v1 = {vals[4], vals[5], vals[6], vals[7]};
        *(float4*)(Cb + (long)(m0 + m) * fo + n0 + tx * 4)      = v0;
        *(float4*)(Cb + (long)(m0 + m) * fo + n0 + 64 + tx * 4) = v1;
    }
}

// ---------------- el/er row dots (warp per row) ----------------
__global__ void rowdots(const float* __restrict__ H, const float* __restrict__ a,
                        float* __restrict__ el, float* __restrict__ er, int Fo)
{
    int row  = blockIdx.x * (blockDim.x >> 5) + (threadIdx.x >> 5);
    int lane = threadIdx.x & 31;
    const float* h = H + (long)row * Fo;
    float sl = 0.f, sr = 0.f;
    for (int c = lane; c < Fo; c += 32) {
        float hv = h[c];
        sl = fmaf(hv, a[c], sl);
        sr = fmaf(hv, a[Fo + c], sr);
    }
    #pragma unroll
    for (int o = 16; o; o >>= 1) {
        sl += __shfl_xor_sync(0xffffffffu, sl, o);
        sr += __shfl_xor_sync(0xffffffffu, sr, o);
    }
    if (lane == 0) { el[row] = sl; er[row] = sr; }
}

// ---------------- per-batch min/max -> {mn, 30/(mx-mn)} ----------------
__global__ void minmax_kernel(const float* __restrict__ el, const float* __restrict__ er,
                              float* __restrict__ prm)
{
    __shared__ float sm[4][8];
    int b = blockIdx.x, tid = threadIdx.x;
    float mnl =  3.4e38f, mxl = -3.4e38f, mnr = 3.4e38f, mxr = -3.4e38f;
    for (int i = tid; i < NN; i += 256) {
        float v = el[b * NN + i]; mnl = fminf(mnl, v); mxl = fmaxf(mxl, v);
        float w = er[b * NN + i]; mnr = fminf(mnr, w); mxr = fmaxf(mxr, w);
    }
    #pragma unroll
    for (int o = 16; o; o >>= 1) {
        mnl = fminf(mnl, __shfl_xor_sync(0xffffffffu, mnl, o));
        mxl = fmaxf(mxl, __shfl_xor_sync(0xffffffffu, mxl, o));
        mnr = fminf(mnr, __shfl_xor_sync(0xffffffffu, mnr, o));
        mxr = fmaxf(mxr, __shfl_xor_sync(0xffffffffu, mxr, o));
    }
    int wid = tid >> 5, lane = tid & 31;
    if (lane == 0) { sm[0][wid] = mnl; sm[1][wid] = mxl; sm[2][wid] = mnr; sm[3][wid] = mxr; }
    __syncthreads();
    if (tid == 0) {
        float a = sm[0][0], c = sm[1][0], d = sm[2][0], e = sm[3][0];
        for (int w = 1; w < 8; w++) {
            a = fminf(a, sm[0][w]); c = fmaxf(c, sm[1][w]);
            d = fminf(d, sm[2][w]); e = fmaxf(e, sm[3][w]);
        }
        float smn = a + d, smx = c + e;   // leaky is monotone
        float emn = (smn >= 0.f) ? smn : 0.01f * smn;
        float emx = (smx >= 0.f) ? smx : 0.01f * smx;
        prm[2 * b]     = emn;
        prm[2 * b + 1] = 30.0f / (emx - emn);
    }
}

// ---------------- gz[r] = g2[r,:] . Wg ----------------
__global__ void gz_kernel(const float* __restrict__ g2, const float* __restrict__ Wg,
                          float* __restrict__ gz)
{
    int row  = blockIdx.x * (blockDim.x >> 5) + (threadIdx.x >> 5);
    int lane = threadIdx.x & 31;
    const float* g = g2 + (long)row * H2D;
    float s = 0.f;
    for (int c = lane; c < H2D; c += 32) s = fmaf(g[c], Wg[c], s);
    #pragma unroll
    for (int o = 16; o; o >>= 1) s += __shfl_xor_sync(0xffffffffu, s, o);
    if (lane == 0) gz[row] = s;
}

// ---------------- out[b,i] = leaky( fc2[b,i,:] . gz[b,:] + bg ) ----------------
__global__ void final_out(const float* __restrict__ fc2, const float* __restrict__ gz,
                          const float* __restrict__ bg, float* __restrict__ out)
{
    int row  = blockIdx.x * (blockDim.x >> 5) + (threadIdx.x >> 5);
    int lane = threadIdx.x & 31;
    int b = row >> 10;
    const float* f = fc2 + (long)row * NN;
    const float* g = gz + b * NN;
    float s = 0.f;
    #pragma unroll 4
    for (int j = lane; j < NN; j += 32) s = fmaf(f[j], g[j], s);
    #pragma unroll
    for (int o = 16; o; o >>= 1) s += __shfl_xor_sync(0xffffffffu, s, o);
    if (lane == 0) {
        float z = s + bg[0];
        out[row] = (z >= 0.f) ? z : 0.01f * z;
    }
}

// ------------------------------- launch ------------------------------------------
extern "C" void kernel_launch(void* const* d_in, const int* in_sizes, int n_in,
                              void* d_out, int out_size)
{
    const float* x  = (const float*)d_in[0];
    const float* W1 = (const float*)d_in[2];
    const float* a1 = (const float*)d_in[3];
    const float* W2 = (const float*)d_in[4];
    const float* a2 = (const float*)d_in[5];
    const float* Wg = (const float*)d_in[6];
    const float* bg = (const float*)d_in[7];

    float* out_z = (float*)d_out;                 // [B,N,1]
    float* fc2   = out_z + ROWS;                  // [B,N,N]
    float* g2    = fc2 + (long)BB * NN * NN;      // [B,N,H2]

    float *p_h1, *p_g1, *p_h2, *p_el1, *p_er1, *p_el2, *p_er2, *p_gz, *p_prm1, *p_prm2;
    cudaGetSymbolAddress((void**)&p_h1,   d_h1);
    cudaGetSymbolAddress((void**)&p_g1,   d_g1);
    cudaGetSymbolAddress((void**)&p_h2,   d_h2);
    cudaGetSymbolAddress((void**)&p_el1,  d_el1);
    cudaGetSymbolAddress((void**)&p_er1,  d_er1);
    cudaGetSymbolAddress((void**)&p_el2,  d_el2);
    cudaGetSymbolAddress((void**)&p_er2,  d_er2);
    cudaGetSymbolAddress((void**)&p_gz,   d_gz);
    cudaGetSymbolAddress((void**)&p_prm1, d_prm1);
    cudaGetSymbolAddress((void**)&p_prm2, d_prm2);

    // 1) h1 = x @ W1   [32768,512]@[512,256]
    gemm128<<<dim3(H1D / 128, ROWS / 128), 256>>>(x, W1, p_h1, ROWS, H1D, FIN);

    // 2) el1/er1 ; 3) norm params
    rowdots<<<ROWS / 8, 256>>>(p_h1, a1, p_el1, p_er1, H1D);
    minmax_kernel<<<BB, 256>>>(p_el1, p_er1, p_prm1);

    // 4) g1 = elu(att1 @ h1), att1 generated on the fly (never materialized)
    attgemm<0, 1><<<dim3(H1D / 128, NN / 128, BB), 256>>>(p_el1, p_er1, p_prm1,
                                                          p_h1, p_g1, nullptr, H1D);

    // 5) h2 = g1 @ W2  [32768,256]@[256,128]
    gemm128<<<dim3(H2D / 128, ROWS / 128), 256>>>(p_g1, W2, p_h2, ROWS, H2D, H1D);

    // 6) el2/er2 ; 7) norm params
    rowdots<<<ROWS / 8, 256>>>(p_h2, a2, p_el2, p_er2, H2D);
    minmax_kernel<<<BB, 256>>>(p_el2, p_er2, p_prm2);

    // 8) g2 = att2 @ h2, att2 generated on the fly AND streamed out as fc2
    attgemm<1, 0><<<dim3(H2D / 128, NN / 128, BB), 256>>>(p_el2, p_er2, p_prm2,
                                                          p_h2, g2, fc2, H2D);

    // 9) gz = g2 @ Wg   (associativity: (fc2@g2)@Wg == fc2@(g2@Wg))
    gz_kernel<<<ROWS / 8, 256>>>(g2, Wg, p_gz);

    // 10) out = leaky(fc2 @ gz + bg)
    final_out<<<ROWS / 8, 256>>>(fc2, p_gz, bg, out_z);
}

// round 5
// speedup vs baseline: 2.2144x; 1.1848x over previous
#include <cuda_runtime.h>
#include <cstdint>

#define BB   32
#define NN   1024
#define FIN  512
#define H1D  256
#define H2D  128
#define ROWS (BB * NN)   // 32768

// ---------------- scratch ----------------
__device__ float d_h1 [ROWS * H1D];
__device__ float d_g1 [ROWS * H1D];
__device__ float d_h2 [ROWS * H2D];
__device__ float d_el1[ROWS], d_er1[ROWS];
__device__ float d_el2[ROWS], d_er2[ROWS];
__device__ float d_gz [ROWS];
__device__ float d_prm1[2 * BB];
__device__ float d_prm2[2 * BB];

// ---------------- tf32 helpers ----------------
__device__ __forceinline__ uint32_t f2tf(float x) {
    uint32_t u;
    asm("cvt.rna.tf32.f32 %0, %1;" : "=r"(u) : "f"(x));
    return u;
}
__device__ __forceinline__ void split_tf32(float x, float& hi, float& lo) {
    uint32_t h = f2tf(x);
    hi = __uint_as_float(h);
    lo = __uint_as_float(f2tf(x - hi));
}
__device__ __forceinline__ void mma8(float c[4], const uint32_t a[4], const uint32_t b[2]) {
    asm volatile(
        "mma.sync.aligned.m16n8k8.row.col.f32.tf32.tf32.f32 "
        "{%0,%1,%2,%3}, {%4,%5,%6,%7}, {%8,%9}, {%0,%1,%2,%3};"
        : "+f"(c[0]), "+f"(c[1]), "+f"(c[2]), "+f"(c[3])
        : "r"(a[0]), "r"(a[1]), "r"(a[2]), "r"(a[3]), "r"(b[0]), "r"(b[1]));
}

// =================================================================================
// Tensor-core GEMM (3xTF32): C[M,N] = A[M,K] @ B[K,N]
// MODE 0: plain A from gmem (weights GEMM, gridDim.z=1)
// MODE 1: A = att(el,er,prm) on the fly, ELU epilogue   (layer-1, batched over z)
// MODE 2: A = att on the fly, att streamed to attOut    (layer-2, batched over z)
// Tile: 128x128, BK=8, 256 threads (8 warps as 2x4), warp tile 64x32 (4x4 mma tiles)
// Double-buffered smem; hi/lo split done once per element at stage time.
// =================================================================================
template<int MODE>
__global__ __launch_bounds__(256, 2)
void tgemm(const float* __restrict__ A, const float* __restrict__ B,
           float* __restrict__ C,
           const float* __restrict__ el, const float* __restrict__ er,
           const float* __restrict__ prm, float* __restrict__ attOut,
           int M, int N, int K)
{
    __shared__ float Ah[2][8][136], Al[2][8][136];
    __shared__ float Bh[2][8][136], Bl[2][8][136];

    const int tid  = threadIdx.x;
    const int wid  = tid >> 5, lane = tid & 31;
    const int g    = lane >> 2, q   = lane & 3;
    const int wm   = (wid >> 2) * 64;    // warp m-offset within tile
    const int wn   = (wid & 3) * 32;     // warp n-offset within tile
    const int m0   = blockIdx.y * 128, n0 = blockIdx.x * 128;
    const int b    = blockIdx.z;

    const float* Bb = B + (long)b * NN * N;   // b==0 for MODE 0
    float*       Cb = C + (long)b * NN * N;

    // loader indices
    const int arow = tid >> 1,  akk  = (tid & 1) * 4;   // A: 128 rows x 8 k
    const int brow = tid >> 5,  bcol = lane * 4;        // B: 8 k-rows x 128 n

    float mn = 0.f, sc = 0.f, elv = 0.f;
    const float* erb = nullptr;
    if (MODE != 0) {
        mn  = prm[2 * b];
        sc  = prm[2 * b + 1];
        elv = el[(long)b * NN + m0 + arow];
        erb = er + (long)b * NN;
    }

    float a4[4], b4[4];

    auto produce = [&](int k0) {
        if (MODE == 0) {
            float4 v = *(const float4*)(A + (long)(m0 + arow) * K + k0 + akk);
            a4[0] = v.x; a4[1] = v.y; a4[2] = v.z; a4[3] = v.w;
        } else {
            float4 e4 = *(const float4*)(erb + k0 + akk);
            float ee[4] = {e4.x, e4.y, e4.z, e4.w};
            #pragma unroll
            for (int i = 0; i < 4; i++) {
                float e = elv + ee[i];
                e = (e >= 0.f) ? e : 0.01f * e;
                float t = (e - mn) * sc - 20.0f;
                a4[i] = 1.0f / (1.0f + __expf(-t));
            }
            if (MODE == 2) {
                *(float4*)(attOut + ((long)b * NN + m0 + arow) * NN + k0 + akk) =
                    make_float4(a4[0], a4[1], a4[2], a4[3]);
            }
        }
        float4 vb = *(const float4*)(Bb + (long)(k0 + brow) * N + n0 + bcol);
        b4[0] = vb.x; b4[1] = vb.y; b4[2] = vb.z; b4[3] = vb.w;
    };

    auto stage = [&](int buf) {
        #pragma unroll
        for (int i = 0; i < 4; i++) {
            float hi, lo; split_tf32(a4[i], hi, lo);
            Ah[buf][akk + i][arow] = hi;
            Al[buf][akk + i][arow] = lo;
        }
        float hv[4], lv[4];
        #pragma unroll
        for (int i = 0; i < 4; i++) split_tf32(b4[i], hv[i], lv[i]);
        *(float4*)&Bh[buf][brow][bcol] = make_float4(hv[0], hv[1], hv[2], hv[3]);
        *(float4*)&Bl[buf][brow][bcol] = make_float4(lv[0], lv[1], lv[2], lv[3]);
    };

    float acc[4][4][4] = {};

    auto compute = [&](int buf) {
        uint32_t bhf[4][2], blf[4][2];
        #pragma unroll
        for (int nt = 0; nt < 4; nt++) {
            int nn = wn + nt * 8 + g;
            bhf[nt][0] = __float_as_uint(Bh[buf][q][nn]);
            bhf[nt][1] = __float_as_uint(Bh[buf][q + 4][nn]);
            blf[nt][0] = __float_as_uint(Bl[buf][q][nn]);
            blf[nt][1] = __float_as_uint(Bl[buf][q + 4][nn]);
        }
        #pragma unroll
        for (int mt = 0; mt < 4; mt++) {
            int mm = wm + mt * 16 + g;
            uint32_t ah[4] = {__float_as_uint(Ah[buf][q][mm]),
                              __float_as_uint(Ah[buf][q][mm + 8]),
                              __float_as_uint(Ah[buf][q + 4][mm]),
                              __float_as_uint(Ah[buf][q + 4][mm + 8])};
            uint32_t al[4] = {__float_as_uint(Al[buf][q][mm]),
                              __float_as_uint(Al[buf][q][mm + 8]),
                              __float_as_uint(Al[buf][q + 4][mm]),
                              __float_as_uint(Al[buf][q + 4][mm + 8])};
            #pragma unroll
            for (int nt = 0; nt < 4; nt++) {
                mma8(acc[mt][nt], ah, bhf[nt]);   // hi*hi
                mma8(acc[mt][nt], ah, blf[nt]);   // hi*lo
                mma8(acc[mt][nt], al, bhf[nt]);   // lo*hi
            }
        }
    };

    const int kt = K >> 3;
    produce(0);
    stage(0);
    __syncthreads();
    for (int t = 0; t < kt; t++) {
        const int buf = t & 1;
        if (t + 1 < kt) produce((t + 1) << 3);
        compute(buf);
        if (t + 1 < kt) stage(buf ^ 1);
        __syncthreads();
    }

    // epilogue
    #pragma unroll
    for (int mt = 0; mt < 4; mt++) {
        #pragma unroll
        for (int nt = 0; nt < 4; nt++) {
            int r0 = m0 + wm + mt * 16 + g;
            int c0 = n0 + wn + nt * 8 + 2 * q;
            float v00 = acc[mt][nt][0], v01 = acc[mt][nt][1];
            float v10 = acc[mt][nt][2], v11 = acc[mt][nt][3];
            if (MODE == 1) {
                v00 = (v00 > 0.f) ? v00 : (__expf(v00) - 1.0f);
                v01 = (v01 > 0.f) ? v01 : (__expf(v01) - 1.0f);
                v10 = (v10 > 0.f) ? v10 : (__expf(v10) - 1.0f);
                v11 = (v11 > 0.f) ? v11 : (__expf(v11) - 1.0f);
            }
            *(float2*)(Cb + (long)r0 * N + c0)       = make_float2(v00, v01);
            *(float2*)(Cb + (long)(r0 + 8) * N + c0) = make_float2(v10, v11);
        }
    }
}

// ---------------- el/er row dots (warp per row) ----------------
__global__ void rowdots(const float* __restrict__ H, const float* __restrict__ a,
                        float* __restrict__ el, float* __restrict__ er, int Fo)
{
    int row  = blockIdx.x * (blockDim.x >> 5) + (threadIdx.x >> 5);
    int lane = threadIdx.x & 31;
    const float* h = H + (long)row * Fo;
    float sl = 0.f, sr = 0.f;
    for (int c = lane; c < Fo; c += 32) {
        float hv = h[c];
        sl = fmaf(hv, a[c], sl);
        sr = fmaf(hv, a[Fo + c], sr);
    }
    #pragma unroll
    for (int o = 16; o; o >>= 1) {
        sl += __shfl_xor_sync(0xffffffffu, sl, o);
        sr += __shfl_xor_sync(0xffffffffu, sr, o);
    }
    if (lane == 0) { el[row] = sl; er[row] = sr; }
}

// ---------------- per-batch min/max -> {mn, 30/(mx-mn)} ----------------
__global__ void minmax_kernel(const float* __restrict__ el, const float* __restrict__ er,
                              float* __restrict__ prm)
{
    __shared__ float sm[4][8];
    int b = blockIdx.x, tid = threadIdx.x;
    float mnl =  3.4e38f, mxl = -3.4e38f, mnr = 3.4e38f, mxr = -3.4e38f;
    for (int i = tid; i < NN; i += 256) {
        float v = el[b * NN + i]; mnl = fminf(mnl, v); mxl = fmaxf(mxl, v);
        float w = er[b * NN + i]; mnr = fminf(mnr, w); mxr = fmaxf(mxr, w);
    }
    #pragma unroll
    for (int o = 16; o; o >>= 1) {
        mnl = fminf(mnl, __shfl_xor_sync(0xffffffffu, mnl, o));
        mxl = fmaxf(mxl, __shfl_xor_sync(0xffffffffu, mxl, o));
        mnr = fminf(mnr, __shfl_xor_sync(0xffffffffu, mnr, o));
        mxr = fmaxf(mxr, __shfl_xor_sync(0xffffffffu, mxr, o));
    }
    int wid = tid >> 5, lane = tid & 31;
    if (lane == 0) { sm[0][wid] = mnl; sm[1][wid] = mxl; sm[2][wid] = mnr; sm[3][wid] = mxr; }
    __syncthreads();
    if (tid == 0) {
        float a = sm[0][0], c = sm[1][0], d = sm[2][0], e = sm[3][0];
        for (int w = 1; w < 8; w++) {
            a = fminf(a, sm[0][w]); c = fmaxf(c, sm[1][w]);
            d = fminf(d, sm[2][w]); e = fmaxf(e, sm[3][w]);
        }
        float smn = a + d, smx = c + e;   // leaky is monotone
        float emn = (smn >= 0.f) ? smn : 0.01f * smn;
        float emx = (smx >= 0.f) ? smx : 0.01f * smx;
        prm[2 * b]     = emn;
        prm[2 * b + 1] = 30.0f / (emx - emn);
    }
}

// ---------------- gz[r] = g2[r,:] . Wg ----------------
__global__ void gz_kernel(const float* __restrict__ g2, const float* __restrict__ Wg,
                          float* __restrict__ gz)
{
    int row  = blockIdx.x * (blockDim.x >> 5) + (threadIdx.x >> 5);
    int lane = threadIdx.x & 31;
    const float* g = g2 + (long)row * H2D;
    float s = 0.f;
    for (int c = lane; c < H2D; c += 32) s = fmaf(g[c], Wg[c], s);
    #pragma unroll
    for (int o = 16; o; o >>= 1) s += __shfl_xor_sync(0xffffffffu, s, o);
    if (lane == 0) gz[row] = s;
}

// ---------------- out[b,i] = leaky( fc2[b,i,:] . gz[b,:] + bg ) ----------------
__global__ void final_out(const float* __restrict__ fc2, const float* __restrict__ gz,
                          const float* __restrict__ bg, float* __restrict__ out)
{
    int row  = blockIdx.x * (blockDim.x >> 5) + (threadIdx.x >> 5);
    int lane = threadIdx.x & 31;
    int b = row >> 10;
    const float* f = fc2 + (long)row * NN;
    const float* g = gz + b * NN;
    float s = 0.f;
    #pragma unroll 4
    for (int j = lane; j < NN; j += 32) s = fmaf(f[j], g[j], s);
    #pragma unroll
    for (int o = 16; o; o >>= 1) s += __shfl_xor_sync(0xffffffffu, s, o);
    if (lane == 0) {
        float z = s + bg[0];
        out[row] = (z >= 0.f) ? z : 0.01f * z;
    }
}

// ------------------------------- launch ------------------------------------------
extern "C" void kernel_launch(void* const* d_in, const int* in_sizes, int n_in,
                              void* d_out, int out_size)
{
    const float* x  = (const float*)d_in[0];
    const float* W1 = (const float*)d_in[2];
    const float* a1 = (const float*)d_in[3];
    const float* W2 = (const float*)d_in[4];
    const float* a2 = (const float*)d_in[5];
    const float* Wg = (const float*)d_in[6];
    const float* bg = (const float*)d_in[7];

    float* out_z = (float*)d_out;                 // [B,N,1]
    float* fc2   = out_z + ROWS;                  // [B,N,N]
    float* g2    = fc2 + (long)BB * NN * NN;      // [B,N,H2]

    float *p_h1, *p_g1, *p_h2, *p_el1, *p_er1, *p_el2, *p_er2, *p_gz, *p_prm1, *p_prm2;
    cudaGetSymbolAddress((void**)&p_h1,   d_h1);
    cudaGetSymbolAddress((void**)&p_g1,   d_g1);
    cudaGetSymbolAddress((void**)&p_h2,   d_h2);
    cudaGetSymbolAddress((void**)&p_el1,  d_el1);
    cudaGetSymbolAddress((void**)&p_er1,  d_er1);
    cudaGetSymbolAddress((void**)&p_el2,  d_el2);
    cudaGetSymbolAddress((void**)&p_er2,  d_er2);
    cudaGetSymbolAddress((void**)&p_gz,   d_gz);
    cudaGetSymbolAddress((void**)&p_prm1, d_prm1);
    cudaGetSymbolAddress((void**)&p_prm2, d_prm2);

    // 1) h1 = x @ W1   [32768,512]@[512,256]
    tgemm<0><<<dim3(H1D / 128, ROWS / 128, 1), 256>>>(
        x, W1, p_h1, nullptr, nullptr, nullptr, nullptr, ROWS, H1D, FIN);

    // 2) el1/er1 ; 3) norm params
    rowdots<<<ROWS / 8, 256>>>(p_h1, a1, p_el1, p_er1, H1D);
    minmax_kernel<<<BB, 256>>>(p_el1, p_er1, p_prm1);

    // 4) g1 = elu(att1 @ h1), att1 generated on the fly (never materialized)
    tgemm<1><<<dim3(H1D / 128, NN / 128, BB), 256>>>(
        nullptr, p_h1, p_g1, p_el1, p_er1, p_prm1, nullptr, NN, H1D, NN);

    // 5) h2 = g1 @ W2  [32768,256]@[256,128]
    tgemm<0><<<dim3(H2D / 128, ROWS / 128, 1), 256>>>(
        p_g1, W2, p_h2, nullptr, nullptr, nullptr, nullptr, ROWS, H2D, H1D);

    // 6) el2/er2 ; 7) norm params
    rowdots<<<ROWS / 8, 256>>>(p_h2, a2, p_el2, p_er2, H2D);
    minmax_kernel<<<BB, 256>>>(p_el2, p_er2, p_prm2);

    // 8) g2 = att2 @ h2, att2 generated on the fly AND streamed out as fc2
    tgemm<2><<<dim3(H2D / 128, NN / 128, BB), 256>>>(
        nullptr, p_h2, g2, p_el2, p_er2, p_prm2, fc2, NN, H2D, NN);

    // 9) gz = g2 @ Wg   (associativity: (fc2@g2)@Wg == fc2@(g2@Wg))
    gz_kernel<<<ROWS / 8, 256>>>(g2, Wg, p_gz);

    // 10) out = leaky(fc2 @ gz + bg)
    final_out<<<ROWS / 8, 256>>>(fc2, p_gz, bg, out_z);
}

// round 6
// speedup vs baseline: 2.2201x; 1.0026x over previous
#include <cuda_runtime.h>
#include <cstdint>

#define BB   32
#define NN   1024
#define FIN  512
#define H1D  256
#define H2D  128
#define ROWS (BB * NN)   // 32768

// ---------------- scratch ----------------
__device__ float d_h1 [ROWS * H1D];
__device__ float d_g1 [ROWS * H1D];
__device__ float d_h2 [ROWS * H2D];
__device__ float d_el1[ROWS], d_er1[ROWS];
__device__ float d_el2[ROWS], d_er2[ROWS];
__device__ float d_gz [ROWS];
__device__ float d_prm1[2 * BB];
__device__ float d_prm2[2 * BB];

// ---------------- tf32 helpers ----------------
__device__ __forceinline__ uint32_t f2tf(float x) {
    uint32_t u;
    asm("cvt.rna.tf32.f32 %0, %1;" : "=r"(u) : "f"(x));
    return u;
}
__device__ __forceinline__ void split_tf32(float x, float& hi, float& lo) {
    uint32_t h = f2tf(x);
    hi = __uint_as_float(h);
    lo = __uint_as_float(f2tf(x - hi));
}
__device__ __forceinline__ void mma8(float c[4], const uint32_t a[4], const uint32_t b[2]) {
    asm volatile(
        "mma.sync.aligned.m16n8k8.row.col.f32.tf32.tf32.f32 "
        "{%0,%1,%2,%3}, {%4,%5,%6,%7}, {%8,%9}, {%0,%1,%2,%3};"
        : "+f"(c[0]), "+f"(c[1]), "+f"(c[2]), "+f"(c[3])
        : "r"(a[0]), "r"(a[1]), "r"(a[2]), "r"(a[3]), "r"(b[0]), "r"(b[1]));
}

// =================================================================================
// Tensor-core GEMM (3xTF32): C[M,N] = A[M,K] @ B[K,N]
// MODE 0: plain A from gmem (weights GEMM, gridDim.z=1)
// MODE 1: A = att(el,er,prm) on the fly, ELU epilogue   (layer-1, batched over z)
// MODE 2: A = att on the fly, att streamed to attOut    (layer-2, batched over z)
// Tile: 128x128, BK=8, 256 threads (8 warps as 2x4), warp tile 64x32 (4x4 mma tiles)
// Double-buffered smem; hi/lo split done once per element at stage time.
// =================================================================================
template<int MODE>
__global__ __launch_bounds__(256, 2)
void tgemm(const float* __restrict__ A, const float* __restrict__ B,
           float* __restrict__ C,
           const float* __restrict__ el, const float* __restrict__ er,
           const float* __restrict__ prm, float* __restrict__ attOut,
           int M, int N, int K)
{
    __shared__ float Ah[2][8][136], Al[2][8][136];
    __shared__ float Bh[2][8][136], Bl[2][8][136];

    const int tid  = threadIdx.x;
    const int wid  = tid >> 5, lane = tid & 31;
    const int g    = lane >> 2, q   = lane & 3;
    const int wm   = (wid >> 2) * 64;    // warp m-offset within tile
    const int wn   = (wid & 3) * 32;     // warp n-offset within tile
    const int m0   = blockIdx.y * 128, n0 = blockIdx.x * 128;
    const int b    = blockIdx.z;

    const float* Bb = B + (long)b * NN * N;   // b==0 for MODE 0
    float*       Cb = C + (long)b * NN * N;

    // loader indices
    const int arow = tid >> 1,  akk  = (tid & 1) * 4;   // A: 128 rows x 8 k
    const int brow = tid >> 5,  bcol = lane * 4;        // B: 8 k-rows x 128 n

    float mn = 0.f, sc = 0.f, elv = 0.f;
    const float* erb = nullptr;
    if (MODE != 0) {
        mn  = prm[2 * b];
        sc  = prm[2 * b + 1];
        elv = el[(long)b * NN + m0 + arow];
        erb = er + (long)b * NN;
    }

    float a4[4], b4[4];

    auto produce = [&](int k0) {
        if (MODE == 0) {
            float4 v = *(const float4*)(A + (long)(m0 + arow) * K + k0 + akk);
            a4[0] = v.x; a4[1] = v.y; a4[2] = v.z; a4[3] = v.w;
        } else {
            float4 e4 = *(const float4*)(erb + k0 + akk);
            float ee[4] = {e4.x, e4.y, e4.z, e4.w};
            #pragma unroll
            for (int i = 0; i < 4; i++) {
                float e = elv + ee[i];
                e = (e >= 0.f) ? e : 0.01f * e;
                float t = (e - mn) * sc - 20.0f;
                a4[i] = 1.0f / (1.0f + __expf(-t));
            }
            if (MODE == 2) {
                *(float4*)(attOut + ((long)b * NN + m0 + arow) * NN + k0 + akk) =
                    make_float4(a4[0], a4[1], a4[2], a4[3]);
            }
        }
        float4 vb = *(const float4*)(Bb + (long)(k0 + brow) * N + n0 + bcol);
        b4[0] = vb.x; b4[1] = vb.y; b4[2] = vb.z; b4[3] = vb.w;
    };

    auto stage = [&](int buf) {
        #pragma unroll
        for (int i = 0; i < 4; i++) {
            float hi, lo; split_tf32(a4[i], hi, lo);
            Ah[buf][akk + i][arow] = hi;
            Al[buf][akk + i][arow] = lo;
        }
        float hv[4], lv[4];
        #pragma unroll
        for (int i = 0; i < 4; i++) split_tf32(b4[i], hv[i], lv[i]);
        *(float4*)&Bh[buf][brow][bcol] = make_float4(hv[0], hv[1], hv[2], hv[3]);
        *(float4*)&Bl[buf][brow][bcol] = make_float4(lv[0], lv[1], lv[2], lv[3]);
    };

    float acc[4][4][4] = {};

    auto compute = [&](int buf) {
        uint32_t bhf[4][2], blf[4][2];
        #pragma unroll
        for (int nt = 0; nt < 4; nt++) {
            int nn = wn + nt * 8 + g;
            bhf[nt][0] = __float_as_uint(Bh[buf][q][nn]);
            bhf[nt][1] = __float_as_uint(Bh[buf][q + 4][nn]);
            blf[nt][0] = __float_as_uint(Bl[buf][q][nn]);
            blf[nt][1] = __float_as_uint(Bl[buf][q + 4][nn]);
        }
        #pragma unroll
        for (int mt = 0; mt < 4; mt++) {
            int mm = wm + mt * 16 + g;
            uint32_t ah[4] = {__float_as_uint(Ah[buf][q][mm]),
                              __float_as_uint(Ah[buf][q][mm + 8]),
                              __float_as_uint(Ah[buf][q + 4][mm]),
                              __float_as_uint(Ah[buf][q + 4][mm + 8])};
            uint32_t al[4] = {__float_as_uint(Al[buf][q][mm]),
                              __float_as_uint(Al[buf][q][mm + 8]),
                              __float_as_uint(Al[buf][q + 4][mm]),
                              __float_as_uint(Al[buf][q + 4][mm + 8])};
            #pragma unroll
            for (int nt = 0; nt < 4; nt++) {
                mma8(acc[mt][nt], ah, bhf[nt]);   // hi*hi
                mma8(acc[mt][nt], ah, blf[nt]);   // hi*lo
                mma8(acc[mt][nt], al, bhf[nt]);   // lo*hi
            }
        }
    };

    const int kt = K >> 3;
    produce(0);
    stage(0);
    __syncthreads();
    for (int t = 0; t < kt; t++) {
        const int buf = t & 1;
        if (t + 1 < kt) produce((t + 1) << 3);
        compute(buf);
        if (t + 1 < kt) stage(buf ^ 1);
        __syncthreads();
    }

    // epilogue
    #pragma unroll
    for (int mt = 0; mt < 4; mt++) {
        #pragma unroll
        for (int nt = 0; nt < 4; nt++) {
            int r0 = m0 + wm + mt * 16 + g;
            int c0 = n0 + wn + nt * 8 + 2 * q;
            float v00 = acc[mt][nt][0], v01 = acc[mt][nt][1];
            float v10 = acc[mt][nt][2], v11 = acc[mt][nt][3];
            if (MODE == 1) {
                v00 = (v00 > 0.f) ? v00 : (__expf(v00) - 1.0f);
                v01 = (v01 > 0.f) ? v01 : (__expf(v01) - 1.0f);
                v10 = (v10 > 0.f) ? v10 : (__expf(v10) - 1.0f);
                v11 = (v11 > 0.f) ? v11 : (__expf(v11) - 1.0f);
            }
            *(float2*)(Cb + (long)r0 * N + c0)       = make_float2(v00, v01);
            *(float2*)(Cb + (long)(r0 + 8) * N + c0) = make_float2(v10, v11);
        }
    }
}

// ---------------- el/er row dots (warp per row) ----------------
__global__ void rowdots(const float* __restrict__ H, const float* __restrict__ a,
                        float* __restrict__ el, float* __restrict__ er, int Fo)
{
    int row  = blockIdx.x * (blockDim.x >> 5) + (threadIdx.x >> 5);
    int lane = threadIdx.x & 31;
    const float* h = H + (long)row * Fo;
    float sl = 0.f, sr = 0.f;
    for (int c = lane; c < Fo; c += 32) {
        float hv = h[c];
        sl = fmaf(hv, a[c], sl);
        sr = fmaf(hv, a[Fo + c], sr);
    }
    #pragma unroll
    for (int o = 16; o; o >>= 1) {
        sl += __shfl_xor_sync(0xffffffffu, sl, o);
        sr += __shfl_xor_sync(0xffffffffu, sr, o);
    }
    if (lane == 0) { el[row] = sl; er[row] = sr; }
}

// ---------------- per-batch min/max -> {mn, 30/(mx-mn)} ----------------
__global__ void minmax_kernel(const float* __restrict__ el, const float* __restrict__ er,
                              float* __restrict__ prm)
{
    __shared__ float sm[4][8];
    int b = blockIdx.x, tid = threadIdx.x;
    float mnl =  3.4e38f, mxl = -3.4e38f, mnr = 3.4e38f, mxr = -3.4e38f;
    for (int i = tid; i < NN; i += 256) {
        float v = el[b * NN + i]; mnl = fminf(mnl, v); mxl = fmaxf(mxl, v);
        float w = er[b * NN + i]; mnr = fminf(mnr, w); mxr = fmaxf(mxr, w);
    }
    #pragma unroll
    for (int o = 16; o; o >>= 1) {
        mnl = fminf(mnl, __shfl_xor_sync(0xffffffffu, mnl, o));
        mxl = fmaxf(mxl, __shfl_xor_sync(0xffffffffu, mxl, o));
        mnr = fminf(mnr, __shfl_xor_sync(0xffffffffu, mnr, o));
        mxr = fmaxf(mxr, __shfl_xor_sync(0xffffffffu, mxr, o));
    }
    int wid = tid >> 5, lane = tid & 31;
    if (lane == 0) { sm[0][wid] = mnl; sm[1][wid] = mxl; sm[2][wid] = mnr; sm[3][wid] = mxr; }
    __syncthreads();
    if (tid == 0) {
        float a = sm[0][0], c = sm[1][0], d = sm[2][0], e = sm[3][0];
        for (int w = 1; w < 8; w++) {
            a = fminf(a, sm[0][w]); c = fmaxf(c, sm[1][w]);
            d = fminf(d, sm[2][w]); e = fmaxf(e, sm[3][w]);
        }
        float smn = a + d, smx = c + e;   // leaky is monotone
        float emn = (smn >= 0.f) ? smn : 0.01f * smn;
        float emx = (smx >= 0.f) ? smx : 0.01f * smx;
        prm[2 * b]     = emn;
        prm[2 * b + 1] = 30.0f / (emx - emn);
    }
}

// ---------------- gz[r] = g2[r,:] . Wg ----------------
__global__ void gz_kernel(const float* __restrict__ g2, const float* __restrict__ Wg,
                          float* __restrict__ gz)
{
    int row  = blockIdx.x * (blockDim.x >> 5) + (threadIdx.x >> 5);
    int lane = threadIdx.x & 31;
    const float* g = g2 + (long)row * H2D;
    float s = 0.f;
    for (int c = lane; c < H2D; c += 32) s = fmaf(g[c], Wg[c], s);
    #pragma unroll
    for (int o = 16; o; o >>= 1) s += __shfl_xor_sync(0xffffffffu, s, o);
    if (lane == 0) gz[row] = s;
}

// ---------------- out[b,i] = leaky( fc2[b,i,:] . gz[b,:] + bg ) ----------------
__global__ void final_out(const float* __restrict__ fc2, const float* __restrict__ gz,
                          const float* __restrict__ bg, float* __restrict__ out)
{
    int row  = blockIdx.x * (blockDim.x >> 5) + (threadIdx.x >> 5);
    int lane = threadIdx.x & 31;
    int b = row >> 10;
    const float* f = fc2 + (long)row * NN;
    const float* g = gz + b * NN;
    float s = 0.f;
    #pragma unroll 4
    for (int j = lane; j < NN; j += 32) s = fmaf(f[j], g[j], s);
    #pragma unroll
    for (int o = 16; o; o >>= 1) s += __shfl_xor_sync(0xffffffffu, s, o);
    if (lane == 0) {
        float z = s + bg[0];
        out[row] = (z >= 0.f) ? z : 0.01f * z;
    }
}

// ------------------------------- launch ------------------------------------------
extern "C" void kernel_launch(void* const* d_in, const int* in_sizes, int n_in,
                              void* d_out, int out_size)
{
    const float* x  = (const float*)d_in[0];
    const float* W1 = (const float*)d_in[2];
    const float* a1 = (const float*)d_in[3];
    const float* W2 = (const float*)d_in[4];
    const float* a2 = (const float*)d_in[5];
    const float* Wg = (const float*)d_in[6];
    const float* bg = (const float*)d_in[7];

    float* out_z = (float*)d_out;                 // [B,N,1]
    float* fc2   = out_z + ROWS;                  // [B,N,N]
    float* g2    = fc2 + (long)BB * NN * NN;      // [B,N,H2]

    float *p_h1, *p_g1, *p_h2, *p_el1, *p_er1, *p_el2, *p_er2, *p_gz, *p_prm1, *p_prm2;
    cudaGetSymbolAddress((void**)&p_h1,   d_h1);
    cudaGetSymbolAddress((void**)&p_g1,   d_g1);
    cudaGetSymbolAddress((void**)&p_h2,   d_h2);
    cudaGetSymbolAddress((void**)&p_el1,  d_el1);
    cudaGetSymbolAddress((void**)&p_er1,  d_er1);
    cudaGetSymbolAddress((void**)&p_el2,  d_el2);
    cudaGetSymbolAddress((void**)&p_er2,  d_er2);
    cudaGetSymbolAddress((void**)&p_gz,   d_gz);
    cudaGetSymbolAddress((void**)&p_prm1, d_prm1);
    cudaGetSymbolAddress((void**)&p_prm2, d_prm2);

    // 1) h1 = x @ W1   [32768,512]@[512,256]
    tgemm<0><<<dim3(H1D / 128, ROWS / 128, 1), 256>>>(
        x, W1, p_h1, nullptr, nullptr, nullptr, nullptr, ROWS, H1D, FIN);

    // 2) el1/er1 ; 3) norm params
    rowdots<<<ROWS / 8, 256>>>(p_h1, a1, p_el1, p_er1, H1D);
    minmax_kernel<<<BB, 256>>>(p_el1, p_er1, p_prm1);

    // 4) g1 = elu(att1 @ h1), att1 generated on the fly (never materialized)
    tgemm<1><<<dim3(H1D / 128, NN / 128, BB), 256>>>(
        nullptr, p_h1, p_g1, p_el1, p_er1, p_prm1, nullptr, NN, H1D, NN);

    // 5) h2 = g1 @ W2  [32768,256]@[256,128]
    tgemm<0><<<dim3(H2D / 128, ROWS / 128, 1), 256>>>(
        p_g1, W2, p_h2, nullptr, nullptr, nullptr, nullptr, ROWS, H2D, H1D);

    // 6) el2/er2 ; 7) norm params
    rowdots<<<ROWS / 8, 256>>>(p_h2, a2, p_el2, p_er2, H2D);
    minmax_kernel<<<BB, 256>>>(p_el2, p_er2, p_prm2);

    // 8) g2 = att2 @ h2, att2 generated on the fly AND streamed out as fc2
    tgemm<2><<<dim3(H2D / 128, NN / 128, BB), 256>>>(
        nullptr, p_h2, g2, p_el2, p_er2, p_prm2, fc2, NN, H2D, NN);

    // 9) gz = g2 @ Wg   (associativity: (fc2@g2)@Wg == fc2@(g2@Wg))
    gz_kernel<<<ROWS / 8, 256>>>(g2, Wg, p_gz);

    // 10) out = leaky(fc2 @ gz + bg)
    final_out<<<ROWS / 8, 256>>>(fc2, p_gz, bg, out_z);
}